// round 12
// baseline (speedup 1.0000x reference)
#include <cuda_runtime.h>

// x: [8,32,512] fp32, w_q/w_k/w_v: [1,128] fp32, out: [8,32,128] fp32
#define BV      256
#define FDIM    512
#define DMODEL  128
#define MNODES  32
#define TPB     512
#define NW      (TPB / 32)      // 16 warps

__device__ __forceinline__ float ex2f(float a) {
    float r; asm("ex2.approx.ftz.f32 %0, %1;" : "=f"(r) : "f"(a)); return r;
}

__global__ __launch_bounds__(TPB)
void attn_cheb_kernel(const float* __restrict__ x,
                      const float* __restrict__ wq,
                      const float* __restrict__ wk,
                      const float* __restrict__ wv,
                      float* __restrict__ out)
{
    __shared__ __align__(16) float sx[FDIM];
    __shared__ float tbl[2 * MNODES];   // tbl[m] = cos(pi*m/64), m<64
    __shared__ float sS[MNODES];        // s(t_j) at Chebyshev nodes
    __shared__ float sC[MNODES];        // Chebyshev coefficients
    __shared__ float sRp[NW], sRmx[NW], sRmn[NW], sRs[NW];

    const int tid  = threadIdx.x;
    const int lane = tid & 31;
    const int warp = tid >> 5;
    const int bv   = blockIdx.x;
    const float* __restrict__ xr = x + bv * FDIM;

    // ---- Phase 1: load row (1/thread), wv hoist, row min/max, K partials ----
    const float wvv = (tid < DMODEL) ? wv[tid] : 0.0f;
    float v = xr[tid];
    sx[tid] = v;
    float lmax = v, lmin = v;
    float p = (tid < DMODEL) ? wq[tid] * wk[tid] : 0.0f;
    #pragma unroll
    for (int s = 16; s > 0; s >>= 1) {
        p   += __shfl_xor_sync(~0u, p, s);
        lmax = fmaxf(lmax, __shfl_xor_sync(~0u, lmax, s));
        lmin = fminf(lmin, __shfl_xor_sync(~0u, lmin, s));
    }
    if (lane == 0) { sRp[warp] = p; sRmx[warp] = lmax; sRmn[warp] = lmin; }
    if (tid < 2 * MNODES) tbl[tid] = cospif((float)tid * (1.0f / (2 * MNODES)));
    __syncthreads();                                                   // B1

    // Every thread redundantly finalizes the block scalars (bitwise identical).
    float P = 0.0f, Mx = sRmx[0], Mn = sRmn[0];
    #pragma unroll
    for (int w = 0; w < NW; w++) {
        P += sRp[w];
        Mx = fmaxf(Mx, sRmx[w]);
        Mn = fminf(Mn, sRmn[w]);
    }
    const float K   = P * (1.4426950408889634f * 0.08838834764831845f); // log2e/sqrt(128)
    const float ta  = K * Mn, tb = K * Mx;
    const float cen = 0.5f * (ta + tb);
    float h = 0.5f * fabsf(tb - ta);
    if (h < 1e-30f) h = 1e-30f;
    const float hinv = 1.0f / h;

    // ---- Phase 2: sample s(t) at 32 nodes; warp w -> nodes w, w+16 ----
    {
        const int j0 = warp, j1 = warp + NW;
        const float tj0 = fmaf(h, tbl[2 * j0 + 1], cen);
        const float tj1 = fmaf(h, tbl[2 * j1 + 1], cen);
        const float Mj0 = (tj0 >= 0.0f) ? tj0 * Mx : tj0 * Mn;
        const float Mj1 = (tj1 >= 0.0f) ? tj1 * Mx : tj1 * Mn;
        float d0a = 0.f, d0b = 0.f, n0a = 0.f, n0b = 0.f;
        float d1a = 0.f, d1b = 0.f, n1a = 0.f, n1b = 0.f;
        const float4* __restrict__ sx4 = (const float4*)sx;
        #pragma unroll
        for (int i = 0; i < FDIM / 128; i++) {      // 4 iters x float4 = 16 g/lane
            float4 g = sx4[lane + 32 * i];
            float e0 = ex2f(fmaf(tj0, g.x, -Mj0));
            float e1 = ex2f(fmaf(tj0, g.y, -Mj0));
            float e2 = ex2f(fmaf(tj0, g.z, -Mj0));
            float e3 = ex2f(fmaf(tj0, g.w, -Mj0));
            float f0 = ex2f(fmaf(tj1, g.x, -Mj1));
            float f1 = ex2f(fmaf(tj1, g.y, -Mj1));
            float f2 = ex2f(fmaf(tj1, g.z, -Mj1));
            float f3 = ex2f(fmaf(tj1, g.w, -Mj1));
            d0a += e0; d0b += e1; d0a += e2; d0b += e3;
            d1a += f0; d1b += f1; d1a += f2; d1b += f3;
            n0a = fmaf(e0, g.x, n0a); n0b = fmaf(e1, g.y, n0b);
            n0a = fmaf(e2, g.z, n0a); n0b = fmaf(e3, g.w, n0b);
            n1a = fmaf(f0, g.x, n1a); n1b = fmaf(f1, g.y, n1b);
            n1a = fmaf(f2, g.z, n1a); n1b = fmaf(f3, g.w, n1b);
        }
        float den0 = d0a + d0b, num0 = n0a + n0b;
        float den1 = d1a + d1b, num1 = n1a + n1b;
        #pragma unroll
        for (int s = 16; s > 0; s >>= 1) {
            den0 += __shfl_xor_sync(~0u, den0, s);
            num0 += __shfl_xor_sync(~0u, num0, s);
            den1 += __shfl_xor_sync(~0u, den1, s);
            num1 += __shfl_xor_sync(~0u, num1, s);
        }
        if (lane == 0) { sS[j0] = num0 / den0; sS[j1] = num1 / den1; }
    }
    __syncthreads();                                                   // B2

    // ---- Phase 3: parallel DCT; warp w -> coefficients w, w+16 ----
    {
        const float sj = sS[lane];          // lane = node index j
        #pragma unroll
        for (int rep = 0; rep < 2; rep++) {
            int k = warp + rep * NW;
            int m = (k * (2 * lane + 1)) & (4 * MNODES - 1);  // angle pi*m/64 mod 2pi
            float c = (m < 2 * MNODES) ? tbl[m] : -tbl[m - 2 * MNODES];
            float a = sj * c;
            #pragma unroll
            for (int s = 16; s > 0; s >>= 1)
                a += __shfl_xor_sync(~0u, a, s);
            if (lane == 0)
                sC[k] = a * (2.0f / MNODES) * (k == 0 ? 0.5f : 1.0f);
        }
    }
    __syncthreads();                                                   // B3

    // ---- Phase 4: Clenshaw eval s(t_f), 1 f per thread ----
    float sf;
    {
        float u = (K * sx[tid] - cen) * hinv;
        u = fminf(fmaxf(u, -1.0f), 1.0f);
        float tu = u + u;
        float b1 = 0.0f, b2 = 0.0f;
        #pragma unroll
        for (int k = MNODES - 1; k >= 1; k--) {
            float b = fmaf(tu, b1, sC[k] - b2);
            b2 = b1; b1 = b;
        }
        sf = fmaf(u, b1, sC[0] - b2);
    }

    // ---- Phase 5: mean over f, write output row (no trailing barrier) ----
    #pragma unroll
    for (int s = 16; s > 0; s >>= 1)
        sf += __shfl_xor_sync(~0u, sf, s);
    if (lane == 0) sRs[warp] = sf;
    __syncthreads();                                                   // B4
    if (tid < DMODEL) {
        float m = 0.0f;
        #pragma unroll
        for (int w = 0; w < NW; w++) m += sRs[w];    // broadcast LDS
        out[bv * DMODEL + tid] = m * (1.0f / 512.0f) * wvv;
    }
}

extern "C" void kernel_launch(void* const* d_in, const int* in_sizes, int n_in,
                              void* d_out, int out_size)
{
    const float* x  = (const float*)d_in[0];
    const float* wq = (const float*)d_in[1];
    const float* wk = (const float*)d_in[2];
    const float* wv = (const float*)d_in[3];
    float* out = (float*)d_out;

    attn_cheb_kernel<<<BV, TPB>>>(x, wq, wk, wv, out);
}